// round 16
// baseline (speedup 1.0000x reference)
#include <cuda_runtime.h>
#include <cuda_bf16.h>
#include <cstdint>

// Per-edge dot product: out[e] = sum_d h[src[e]][d] * h[dst[e]][d]
// E = 1e6, D = 256, N = 1e5.
//
// R16 (= R12 resubmit #4; broker/infra failures, never executed):
// persistent warps + TWO-DEEP row-load pipeline. R11 (129 us) still
// stalled each iteration on its own 4 row loads (issue 30%, occ 47%).
// Now pair k+1's row loads are issued before pair k's data is consumed
// (double-buffered 2x32 data regs), and pair k+1's indices were loaded one
// iteration earlier. Steady state: warp never waits a full row latency.
// 128-thr blocks for occupancy packing at ~90 regs (~20 warps/SM).

#ifndef D_FEAT
#define D_FEAT 256
#endif

__device__ int g_idx_is_64 = 1;

// int64 data in [0, n_nodes) -> every 8-byte word valid. int32 data decodes
// as v0 + v1*2^32, out of range unless v1==0; 64 probes all passing by
// accident ~1e-320.
__global__ void detect_idx_kernel(const void* __restrict__ src_raw,
                                  long long n_nodes) {
    if (blockIdx.x == 0 && threadIdx.x == 0) {
        const long long* p = (const long long*)src_raw;
        int ok = 1;
        #pragma unroll 1
        for (int i = 0; i < 64; i++) {
            long long v = p[i];
            if (v < 0 || v >= n_nodes) { ok = 0; break; }
        }
        g_idx_is_64 = ok;
    }
}

struct F8 { float v[8]; };

// 256-bit table-row load (rows 1KB-aligned, lane offsets 32B).
__device__ __forceinline__ F8 ldg256_el(const float* p) {
    F8 r;
    asm("ld.global.nc.L2::evict_last.v8.b32 "
        "{%0,%1,%2,%3,%4,%5,%6,%7}, [%8];"
        : "=f"(r.v[0]), "=f"(r.v[1]), "=f"(r.v[2]), "=f"(r.v[3]),
          "=f"(r.v[4]), "=f"(r.v[5]), "=f"(r.v[6]), "=f"(r.v[7])
        : "l"(p));
    return r;
}

__device__ __forceinline__ void load_pair_idx(
    const void* __restrict__ src_raw, const void* __restrict__ dst_raw,
    bool is64, int e0, int n_edges,
    int& s0, int& d0, int& s1, int& d1)
{
    const bool has1 = (e0 + 1 < n_edges);
    if (is64) {
        const long long* sp = (const long long*)src_raw;
        const long long* dp = (const long long*)dst_raw;
        s0 = (int)__ldcs(sp + e0);
        d0 = (int)__ldcs(dp + e0);
        s1 = has1 ? (int)__ldcs(sp + e0 + 1) : s0;
        d1 = has1 ? (int)__ldcs(dp + e0 + 1) : d0;
    } else {
        const int* sp = (const int*)src_raw;
        const int* dp = (const int*)dst_raw;
        s0 = __ldcs(sp + e0);
        d0 = __ldcs(dp + e0);
        s1 = has1 ? __ldcs(sp + e0 + 1) : s0;
        d1 = has1 ? __ldcs(dp + e0 + 1) : d0;
    }
}

__device__ __forceinline__ void issue_rows(
    const float* __restrict__ h, int fo,
    int s0, int d0, int s1, int d1,
    F8& a, F8& b, F8& c, F8& f)
{
    a = ldg256_el(h + (long long)s0 * D_FEAT + fo);
    b = ldg256_el(h + (long long)d0 * D_FEAT + fo);
    c = ldg256_el(h + (long long)s1 * D_FEAT + fo);
    f = ldg256_el(h + (long long)d1 * D_FEAT + fo);
}

__device__ __forceinline__ void consume_pair(
    const F8& a, const F8& b, const F8& c, const F8& f,
    float* __restrict__ out, int e0, int n_edges, int lane)
{
    float acc0 = a.v[0] * b.v[0];
    #pragma unroll
    for (int i = 1; i < 8; i++) acc0 = fmaf(a.v[i], b.v[i], acc0);
    float acc1 = c.v[0] * f.v[0];
    #pragma unroll
    for (int i = 1; i < 8; i++) acc1 = fmaf(c.v[i], f.v[i], acc1);

    #pragma unroll
    for (int off = 16; off > 0; off >>= 1) {
        acc0 += __shfl_xor_sync(0xFFFFFFFFu, acc0, off);
        acc1 += __shfl_xor_sync(0xFFFFFFFFu, acc1, off);
    }
    if (lane == 0) {
        __stcs(out + e0, acc0);
        if (e0 + 1 < n_edges) __stcs(out + e0 + 1, acc1);
    }
}

__global__ __launch_bounds__(128)
void edge_dot_kernel(const float* __restrict__ h,
                     const void* __restrict__ src_raw,
                     const void* __restrict__ dst_raw,
                     float* __restrict__ out,
                     int n_edges) {
    const int lane = threadIdx.x & 31;
    const int warp = (int)((blockIdx.x * blockDim.x + threadIdx.x) >> 5);
    const int S = (int)((gridDim.x * blockDim.x) >> 5);   // total warps
    const int n_pairs = (n_edges + 1) >> 1;
    const bool is64 = (g_idx_is_64 != 0);
    const int fo = lane * 8;

    int pc = warp;
    if (pc >= n_pairs) return;

    F8 A0, A1, A2, A3, B0, B1, B2, B3;
    int s0, d0, s1, d1;

    // Prologue: idx(pc) -> rows(pc) into A; then idx(pn) in flight.
    load_pair_idx(src_raw, dst_raw, is64, 2 * pc, n_edges, s0, d0, s1, d1);
    issue_rows(h, fo, s0, d0, s1, d1, A0, A1, A2, A3);
    int pn = pc + S;
    bool more = (pn < n_pairs);
    if (more)
        load_pair_idx(src_raw, dst_raw, is64, 2 * pn, n_edges, s0, d0, s1, d1);

    #pragma unroll 1
    while (true) {
        // --- consume A (pair pc), fill B (pair pn) ---
        if (more) issue_rows(h, fo, s0, d0, s1, d1, B0, B1, B2, B3);
        {
            int pn2 = pn + S;
            bool more2 = more && (pn2 < n_pairs);
            if (more2)
                load_pair_idx(src_raw, dst_raw, is64, 2 * pn2, n_edges,
                              s0, d0, s1, d1);
            consume_pair(A0, A1, A2, A3, out, 2 * pc, n_edges, lane);
            if (!more) return;
            pc = pn; pn = pn2; more = more2;
        }
        // --- consume B (pair pc), fill A (pair pn) ---
        if (more) issue_rows(h, fo, s0, d0, s1, d1, A0, A1, A2, A3);
        {
            int pn2 = pn + S;
            bool more2 = more && (pn2 < n_pairs);
            if (more2)
                load_pair_idx(src_raw, dst_raw, is64, 2 * pn2, n_edges,
                              s0, d0, s1, d1);
            consume_pair(B0, B1, B2, B3, out, 2 * pc, n_edges, lane);
            if (!more) return;
            pc = pn; pn = pn2; more = more2;
        }
    }
}

extern "C" void kernel_launch(void* const* d_in, const int* in_sizes, int n_in,
                              void* d_out, int out_size) {
    const float* h   = (const float*)d_in[0];
    const void*  src = d_in[1];
    const void*  dst = d_in[2];
    float* out = (float*)d_out;

    // Output is [E, 1] float32 -> out_size == E, independent of index dtype.
    const int n_edges = out_size;
    const long long n_nodes = (long long)(in_sizes[0] / D_FEAT);

    detect_idx_kernel<<<1, 32>>>(src, n_nodes);

    // Persistent grid: 128-thr blocks (4 warps), ~5 blocks/SM on 152 SMs.
    const int n_pairs = (n_edges + 1) / 2;
    const int warps_per_block = 128 / 32;
    int blocks = (n_pairs + warps_per_block - 1) / warps_per_block;
    if (blocks > 760) blocks = 760;
    edge_dot_kernel<<<blocks, 128>>>(h, src, dst, out, n_edges);
}